// round 13
// baseline (speedup 1.0000x reference)
#include <cuda_runtime.h>

// ---------------------------------------------------------------------------
// Threshold_weights7: per-row top-2 margins over 8 predictors [N,128],
// softmax(margins/2) over 8 predictors, plus global max of predictors 0..6.
// Memory-bound: 512MB read. FOUR rows per warp (8 lanes x 16 floats); loads
// in 4 simple batches of 2 preds (8 x LDG.128 burst each, NO pipelining);
// 3-step butterflies amortized over 4 rows. Persistent grid 148x4, one wave.
// ---------------------------------------------------------------------------

static constexpr int kC = 128;     // class dim
static constexpr int kGrid = 592;  // 148 SMs x 4 blocks/SM, single wave

__device__ unsigned g_max_key;  // zero-init at load; self-reset every call
__device__ unsigned g_ticket;

__device__ __forceinline__ unsigned f2key(float f) {
    unsigned u = __float_as_uint(f);
    return (u & 0x80000000u) ? ~u : (u | 0x80000000u);
}

__device__ __forceinline__ float sel4(float4 q, int tsub) {
    return (tsub == 0) ? q.x : (tsub == 1) ? q.y : (tsub == 2) ? q.z : q.w;
}

// top-2 margin for one predictor; row = 8 lanes x 16 floats (v[0..3]).
// Returns margin; M1out = exact row max.
__device__ __forceinline__ float margin8(const float4* v, int towner,
                                         int tq, int tsub, float& M1out) {
    // lane-local top-2 of 16 values
    float H[4], S[4];
#pragma unroll
    for (int i = 0; i < 4; i++) {
        float a1 = fmaxf(v[i].x, v[i].y), a2 = fminf(v[i].x, v[i].y);
        float b1 = fmaxf(v[i].z, v[i].w), b2 = fminf(v[i].z, v[i].w);
        H[i] = fmaxf(a1, b1);
        S[i] = fmaxf(fminf(a1, b1), fmaxf(a2, b2));
    }
    float h01 = fmaxf(H[0], H[1]), s01 = fmaxf(fminf(H[0], H[1]), fmaxf(S[0], S[1]));
    float h23 = fmaxf(H[2], H[3]), s23 = fmaxf(fminf(H[2], H[3]), fmaxf(S[2], S[3]));
    float m1 = fmaxf(h01, h23);
    float m2 = fmaxf(fminf(h01, h23), fmaxf(s01, s23));

    // target logit: element tsub of float4 tq, from lane towner (in group)
    float c01 = (tq & 1) ? sel4(v[1], tsub) : sel4(v[0], tsub);
    float c23 = (tq & 1) ? sel4(v[3], tsub) : sel4(v[2], tsub);
    float tl  = (tq & 2) ? c23 : c01;
    float tv  = __shfl_sync(0xffffffffu, tl, towner, 8);

    // 3-step butterfly top-2 merge within the 8-lane group
#pragma unroll
    for (int off = 4; off; off >>= 1) {
        float o1 = __shfl_xor_sync(0xffffffffu, m1, off);
        float o2 = __shfl_xor_sync(0xffffffffu, m2, off);
        float n2 = fmaxf(fminf(m1, o1), fmaxf(m2, o2));
        m1 = fmaxf(m1, o1);
        m2 = n2;
    }
    M1out = m1;
    return (tv == m1) ? (m1 - m2) : 0.0f;  // exact-equality tie semantics
}

__global__ void __launch_bounds__(256, 4)
k_main(const float* __restrict__ p0, const float* __restrict__ p1,
       const float* __restrict__ p2, const float* __restrict__ p3,
       const float* __restrict__ p4, const float* __restrict__ p5,
       const float* __restrict__ p6, const float* __restrict__ p7,
       const int* __restrict__ targets,
       float* __restrict__ out,   // [has_scalar + N*8]
       int nrows, int has_scalar)
{
    __shared__ unsigned s_gm[8];

    const int lane = threadIdx.x & 31;
    const int wib  = threadIdx.x >> 5;       // warp in block (0..7)
    const int grp  = lane >> 3;              // row group 0..3
    const int gl   = lane & 7;               // lane within group

    const int gwarp  = blockIdx.x * 8 + wib;
    const int nwarps = gridDim.x * 8;

    float* __restrict__ thr = out + has_scalar;
    const float* preds[8] = {p0, p1, p2, p3, p4, p5, p6, p7};

    float gm = -3.402823466e38f;   // running max over predictors 0..6

    const int nquads = (nrows + 3) >> 2;
    for (int q = gwarp; q < nquads; q += nwarps) {
        const int row = q * 4 + grp;
        const bool rowok = (row < nrows);
        const int rsafe = rowok ? row : (nrows - 1);

        const int t = __ldg(targets + rsafe);
        const int towner = t >> 4;        // lane-in-group holding the target
        const int tq     = (t >> 2) & 3;  // which float4 of that lane
        const int tsub   = t & 3;         // element within float4

        const size_t base = (size_t)rsafe * kC + gl * 16;

        float m[8];

        // 4 batches of 2 predictors: 8 LDG.128 burst per batch (depth 8,
        // identical to the R11 winner), 32 live data regs.
#pragma unroll
        for (int b = 0; b < 4; b++) {
            float4 va[4], vb[4];
            const float* pa = preds[b * 2 + 0];
            const float* pb = preds[b * 2 + 1];
#pragma unroll
            for (int i = 0; i < 4; i++) {
                va[i] = __ldcs(reinterpret_cast<const float4*>(pa + base) + i);
                vb[i] = __ldcs(reinterpret_cast<const float4*>(pb + base) + i);
            }

            float M1;
            m[b * 2 + 0] = margin8(va, towner, tq, tsub, M1);
            if (rowok) gm = fmaxf(gm, M1);              // preds 0..6 count
            m[b * 2 + 1] = margin8(vb, towner, tq, tsub, M1);
            if (b < 3 && rowok) gm = fmaxf(gm, M1);     // pred 7 (mimic): no
        }

        // softmax over the 8 margins, T=2 (redundant in group; serves 4 rows)
        float mm = m[0];
#pragma unroll
        for (int p = 1; p < 8; p++) mm = fmaxf(mm, m[p]);
        float s = 0.0f;
#pragma unroll
        for (int p = 0; p < 8; p++) { m[p] = __expf((m[p] - mm) * 0.5f); s += m[p]; }
        const float inv = 1.0f / s;

        if (rowok) {
            float mine = (gl == 0) ? m[0] : (gl == 1) ? m[1]
                       : (gl == 2) ? m[2] : (gl == 3) ? m[3]
                       : (gl == 4) ? m[4] : (gl == 5) ? m[5]
                       : (gl == 6) ? m[6] : m[7];
            thr[(size_t)row * 8 + gl] = mine * inv;  // warp: dense 128B store
        }
    }

    // ---- global-max finalize (last-block ticket) ----
    gm = fmaxf(gm, __shfl_xor_sync(0xffffffffu, gm, 8));   // merge 4 groups
    gm = fmaxf(gm, __shfl_xor_sync(0xffffffffu, gm, 16));
    if (lane == 0) s_gm[wib] = f2key(gm);
    __syncthreads();
    if (threadIdx.x == 0) {
        unsigned k = s_gm[0];
#pragma unroll
        for (int i = 1; i < 8; i++) k = max(k, s_gm[i]);
        atomicMax(&g_max_key, k);
        __threadfence();
        unsigned old = atomicAdd(&g_ticket, 1u);
        if (old == gridDim.x - 1) {
            unsigned kk = g_max_key;
            if (has_scalar) {
                unsigned u = (kk & 0x80000000u) ? (kk & 0x7FFFFFFFu) : ~kk;
                out[0] = __uint_as_float(u);
            }
            g_max_key = 0u;   // reset for next graph replay
            g_ticket  = 0u;
        }
    }
}

extern "C" void kernel_launch(void* const* d_in, const int* in_sizes, int n_in,
                              void* d_out, int out_size)
{
    const float* p[8];
    for (int i = 0; i < 8; i++) p[i] = (const float*)d_in[i];
    const int* targets = (const int*)d_in[8];
    const int nrows = in_sizes[8];           // targets element count == N

    float* out = (float*)d_out;
    int has_scalar = out_size - nrows * 8;
    if (has_scalar < 0) has_scalar = 0;

    k_main<<<kGrid, 256>>>(p[0], p[1], p[2], p[3], p[4], p[5], p[6], p[7],
                           targets, out, nrows, has_scalar);
}

// round 14
// speedup vs baseline: 1.0695x; 1.0695x over previous
#include <cuda_runtime.h>

// ---------------------------------------------------------------------------
// Threshold_weights7: per-row top-2 margins over 8 predictors [N,128],
// softmax(margins/2) over 8 predictors, plus global max of predictors 0..6.
// Memory-bound: 512MB read; measured chip ceiling ~6.5 TB/s (LTS cap at NAT
// clock). Winning shape (R11): TWO rows per warp, 2 reg-batches of 4 preds
// (8xLDG.128 bursts), 4 blocks/SM, persistent single-wave grid. This round:
// streaming stores + minor ALU trims only — load shape untouched.
// ---------------------------------------------------------------------------

static constexpr int kC = 128;     // class dim
static constexpr int kGrid = 592;  // 148 SMs x 4 blocks/SM, single wave

__device__ unsigned g_max_key;  // zero-init at load; self-reset every call
__device__ unsigned g_ticket;

__device__ __forceinline__ unsigned f2key(float f) {
    unsigned u = __float_as_uint(f);
    return (u & 0x80000000u) ? ~u : (u | 0x80000000u);
}

__device__ __forceinline__ void stcs(float* p, float v) {
    asm volatile("st.global.cs.f32 [%0], %1;" :: "l"(p), "f"(v) : "memory");
}

__global__ void __launch_bounds__(256, 4)
k_main(const float* __restrict__ p0, const float* __restrict__ p1,
       const float* __restrict__ p2, const float* __restrict__ p3,
       const float* __restrict__ p4, const float* __restrict__ p5,
       const float* __restrict__ p6, const float* __restrict__ p7,
       const int* __restrict__ targets,
       float* __restrict__ out,   // [has_scalar + N*8]
       int nrows, int has_scalar)
{
    __shared__ unsigned s_gm[8];

    const int lane = threadIdx.x & 31;
    const int wib  = threadIdx.x >> 5;              // warp in block (0..7)
    const int half = lane >> 4;                     // 0: row A, 1: row B
    const int hl   = lane & 15;                     // lane within half

    const int gwarp  = blockIdx.x * 8 + wib;
    const int nwarps = gridDim.x * 8;

    float* __restrict__ thr = out + has_scalar;
    const float* preds[8] = {p0, p1, p2, p3, p4, p5, p6, p7};

    float gm = -3.402823466e38f;   // running max over predictors 0..6

    const int npairs = (nrows + 1) >> 1;
    for (int pair = gwarp; pair < npairs; pair += nwarps) {
        const int row = pair * 2 + half;
        const bool rowok = (row < nrows);
        const int rsafe = rowok ? row : (nrows - 1);

        const int t = __ldcs(targets + rsafe);
        const int towner = t >> 3;       // lane-in-half holding the target
        const int tq     = (t >> 2) & 1; // which float4
        const int tsub   = t & 3;        // element within float4

        const size_t base = (size_t)rsafe * kC + hl * 8;

        float m[8];

        // Two batches of 4 predictors: 8 LDG.128 in flight per batch,
        // 32 data regs -> 4 blocks/SM.  (Load shape = the R11 winner.)
#pragma unroll
        for (int b = 0; b < 2; b++) {
            float4 va[4], vb[4];
#pragma unroll
            for (int p = 0; p < 4; p++) {
                const float* pr = preds[b * 4 + p];
                va[p] = __ldcs(reinterpret_cast<const float4*>(pr + base));
                vb[p] = __ldcs(reinterpret_cast<const float4*>(pr + base + 4));
            }

#pragma unroll
            for (int p = 0; p < 4; p++) {
                const float4 qa = va[p], qb = vb[p];
                // lane-local top-2 of 8 values
                float a1 = fmaxf(qa.x, qa.y), a2 = fminf(qa.x, qa.y);
                float b1 = fmaxf(qa.z, qa.w), b2 = fminf(qa.z, qa.w);
                float m1a = fmaxf(a1, b1);
                float m2a = fmaxf(fminf(a1, b1), fmaxf(a2, b2));
                float c1 = fmaxf(qb.x, qb.y), c2 = fminf(qb.x, qb.y);
                float d1 = fmaxf(qb.z, qb.w), d2 = fminf(qb.z, qb.w);
                float m1b = fmaxf(c1, d1);
                float m2b = fmaxf(fminf(c1, d1), fmaxf(c2, d2));
                float m1 = fmaxf(m1a, m1b);
                float m2 = fmaxf(fminf(m1a, m1b), fmaxf(m2a, m2b));

                // target logit: choose the float4 half first, then element
                float tx = tq ? qb.x : qa.x;
                float ty = tq ? qb.y : qa.y;
                float tz = tq ? qb.z : qa.z;
                float tw = tq ? qb.w : qa.w;
                float tl = (tsub == 0) ? tx : (tsub == 1) ? ty
                         : (tsub == 2) ? tz : tw;
                float tv = __shfl_sync(0xffffffffu, tl, towner, 16);

                // 4-step butterfly top-2 merge within the 16-lane half
#pragma unroll
                for (int off = 8; off; off >>= 1) {
                    float o1 = __shfl_xor_sync(0xffffffffu, m1, off);
                    float o2 = __shfl_xor_sync(0xffffffffu, m2, off);
                    float n2 = fmaxf(fminf(m1, o1), fmaxf(m2, o2));
                    m1 = fmaxf(m1, o1);
                    m2 = n2;
                }
                // margin: exact-equality tie semantics of the reference
                m[b * 4 + p] = (tv == m1) ? (m1 - m2) : 0.0f;
                if ((b * 4 + p) < 7 && rowok) gm = fmaxf(gm, m1);
            }
        }

        // softmax over the 8 margins, T=2 (redundant across the half; cheap)
        float mm = m[0];
#pragma unroll
        for (int p = 1; p < 8; p++) mm = fmaxf(mm, m[p]);
        float s = 0.0f;
#pragma unroll
        for (int p = 0; p < 8; p++) { m[p] = __expf((m[p] - mm) * 0.5f); s += m[p]; }
        const float inv = 1.0f / s;

        if (hl < 8 && rowok) {
            float mine = (hl == 0) ? m[0] : (hl == 1) ? m[1]
                       : (hl == 2) ? m[2] : (hl == 3) ? m[3]
                       : (hl == 4) ? m[4] : (hl == 5) ? m[5]
                       : (hl == 6) ? m[6] : m[7];
            stcs(thr + (size_t)row * 8 + hl, mine * inv);  // streaming store
        }
    }

    // ---- global-max finalize in the same kernel (last-block ticket) ----
    gm = fmaxf(gm, __shfl_xor_sync(0xffffffffu, gm, 16));  // merge both halves
    if (lane == 0) s_gm[wib] = f2key(gm);
    __syncthreads();
    if (threadIdx.x == 0) {
        unsigned k = s_gm[0];
#pragma unroll
        for (int i = 1; i < 8; i++) k = max(k, s_gm[i]);
        atomicMax(&g_max_key, k);
        __threadfence();
        unsigned old = atomicAdd(&g_ticket, 1u);
        if (old == gridDim.x - 1) {
            unsigned kk = g_max_key;
            if (has_scalar) {
                unsigned u = (kk & 0x80000000u) ? (kk & 0x7FFFFFFFu) : ~kk;
                out[0] = __uint_as_float(u);
            }
            g_max_key = 0u;   // reset for next graph replay
            g_ticket  = 0u;
        }
    }
}

extern "C" void kernel_launch(void* const* d_in, const int* in_sizes, int n_in,
                              void* d_out, int out_size)
{
    const float* p[8];
    for (int i = 0; i < 8; i++) p[i] = (const float*)d_in[i];
    const int* targets = (const int*)d_in[8];
    const int nrows = in_sizes[8];           // targets element count == N

    float* out = (float*)d_out;
    int has_scalar = out_size - nrows * 8;
    if (has_scalar < 0) has_scalar = 0;

    k_main<<<kGrid, 256>>>(p[0], p[1], p[2], p[3], p[4], p[5], p[6], p[7],
                           targets, out, nrows, has_scalar);
}